// round 14
// baseline (speedup 1.0000x reference)
#include <cuda_runtime.h>
#include <cstdint>
#include <math_constants.h>

#define DCOLS 2048
#define THREADS 256
#define CAP 256

__device__ __forceinline__ void stwt4(float4* p, float4 v) {
    // Write-through store: don't allocate the write-once output stream in L2.
    asm volatile("st.global.wt.v4.f32 [%0], {%1, %2, %3, %4};"
                 :: "l"(p), "f"(v.x), "f"(v.y), "f"(v.z), "f"(v.w) : "memory");
}

__device__ __forceinline__ float michelot_list(const float* c, int k) {
    // Exact sparsemax threshold over candidate list c[0..k) (all finite, > max-1).
    float S = 0.f;
    for (int i = 0; i < k; i++) S += c[i];
    float tau = (S - 1.0f) / (float)k;
    int prevc = k;
    for (int it = 0; it < CAP + 2; it++) {
        float s = 0.f; int cc = 0;
        for (int i = 0; i < k; i++) {
            float z = c[i];
            if (z > tau) { s += z; cc++; }
        }
        if (cc == prevc || cc == 0) break;
        tau = (s - 1.0f) / (float)cc;
        prevc = cc;
    }
    return tau;
}

__device__ float michelot_row_global(const float* xr, const int* mr) {
    // Fallback (statistically unreachable): serial Michelot over full row.
    float S = 0.f; int k = 0;
    for (int i = 0; i < DCOLS; i++) if (mr[i]) { S += xr[i]; k++; }
    float tau = (S - 1.0f) / (float)k;
    int prevc = k;
    for (int it = 0; it < DCOLS + 2; it++) {
        float s = 0.f; int cc = 0;
        for (int i = 0; i < DCOLS; i++) {
            if (mr[i]) { float z = xr[i]; if (z > tau) { s += z; cc++; } }
        }
        if (cc == prevc || cc == 0) break;
        tau = (s - 1.0f) / (float)cc;
        prevc = cc;
    }
    return tau;
}

__global__ __launch_bounds__(THREADS, 8) void sparsemax_kernel(
    const float* __restrict__ x,
    const int* __restrict__ mask,
    float* __restrict__ out)
{
    const int row = blockIdx.x;
    const int t = threadIdx.x;
    const int warp = t >> 5, lane = t & 31;

    const float4* xr = reinterpret_cast<const float4*>(x + (size_t)row * DCOLS);
    const int4*   mr = reinterpret_cast<const int4*>(mask + (size_t)row * DCOLS);
    float4* orow = reinterpret_cast<float4*>(out + (size_t)row * DCOLS);

    __shared__ float s_wmax[8];
    __shared__ int   s_cnt;
    __shared__ float s_tau;
    __shared__ float s_cand[CAP];

    // Load 8 values + 8 mask words, fold mask immediately: inactive -> -inf.
    float4 v0 = xr[t];
    float4 v1 = xr[t + THREADS];
    int4 m0 = mr[t];
    int4 m1 = mr[t + THREADS];

    float vals[8];
    vals[0] = m0.x ? v0.x : -CUDART_INF_F;
    vals[1] = m0.y ? v0.y : -CUDART_INF_F;
    vals[2] = m0.z ? v0.z : -CUDART_INF_F;
    vals[3] = m0.w ? v0.w : -CUDART_INF_F;
    vals[4] = m1.x ? v1.x : -CUDART_INF_F;
    vals[5] = m1.y ? v1.y : -CUDART_INF_F;
    vals[6] = m1.z ? v1.z : -CUDART_INF_F;
    vals[7] = m1.w ? v1.w : -CUDART_INF_F;

    // ---- Phase 1: block max (max alone decides: max is always a candidate) ----
    float mx = vals[0];
    #pragma unroll
    for (int i = 1; i < 8; i++) mx = fmaxf(mx, vals[i]);
    #pragma unroll
    for (int o = 16; o; o >>= 1)
        mx = fmaxf(mx, __shfl_xor_sync(0xFFFFFFFFu, mx, o));
    if (lane == 0) s_wmax[warp] = mx;
    if (t == 0) s_cnt = 0;
    __syncthreads();
    float allmax = s_wmax[0];
    #pragma unroll
    for (int i = 1; i < 8; i++) allmax = fmaxf(allmax, s_wmax[i]);

    // ---- Phase 2: warp-aggregated compaction of {v > max-1} ----
    // (if row is all-inactive: allmax=-inf, thresh=-inf, -inf > -inf false -> k=0)
    const float thresh = allmax - 1.0f;
    #pragma unroll
    for (int i = 0; i < 8; i++) {
        const bool p = vals[i] > thresh;
        const unsigned b = __ballot_sync(0xFFFFFFFFu, p);
        if (b) {
            const int leader = __ffs(b) - 1;
            int base = 0;
            if (lane == leader) base = atomicAdd(&s_cnt, __popc(b));
            base = __shfl_sync(0xFFFFFFFFu, base, leader);
            if (p) {
                int idx = base + __popc(b & ((1u << lane) - 1u));
                if (idx < CAP) s_cand[idx] = vals[i];
            }
        }
    }
    __syncthreads();
    const int k = s_cnt;

    // ---- Phase 3: exact threshold (serial, tiny candidate set) ----
    if (t == 0) {
        float tau;
        if (k == 0)        tau = CUDART_INF_F;            // all-inactive row -> zeros
        else if (k <= CAP) tau = michelot_list(s_cand, k);
        else               tau = michelot_row_global(x + (size_t)row * DCOLS,
                                                     mask + (size_t)row * DCOLS);
        s_tau = tau;
    }
    __syncthreads();
    const float tau = s_tau;

    // ---- Phase 4: p = relu(v - tau); -inf entries give 0 automatically ----
    float4 o0, o1;
    o0.x = fmaxf(vals[0] - tau, 0.f);
    o0.y = fmaxf(vals[1] - tau, 0.f);
    o0.z = fmaxf(vals[2] - tau, 0.f);
    o0.w = fmaxf(vals[3] - tau, 0.f);
    o1.x = fmaxf(vals[4] - tau, 0.f);
    o1.y = fmaxf(vals[5] - tau, 0.f);
    o1.z = fmaxf(vals[6] - tau, 0.f);
    o1.w = fmaxf(vals[7] - tau, 0.f);
    stwt4(&orow[t], o0);
    stwt4(&orow[t + THREADS], o1);
}

extern "C" void kernel_launch(void* const* d_in, const int* in_sizes, int n_in,
                              void* d_out, int out_size) {
    const float* x = (const float*)d_in[0];
    const int* mask = (const int*)d_in[1];
    float* out = (float*)d_out;

    const int rows = out_size / DCOLS;   // 16384
    sparsemax_kernel<<<rows, THREADS>>>(x, mask, out);
}

// round 15
// speedup vs baseline: 1.0004x; 1.0004x over previous
#include <cuda_runtime.h>
#include <cstdint>
#include <math_constants.h>

#define DCOLS 2048
#define THREADS 256
#define CAP 256

__device__ __forceinline__ float michelot_list(const float* c, int k) {
    // Exact sparsemax threshold over candidate list c[0..k) (all finite, > max-1).
    float S = 0.f;
    for (int i = 0; i < k; i++) S += c[i];
    float tau = (S - 1.0f) / (float)k;
    int prevc = k;
    for (int it = 0; it < CAP + 2; it++) {
        float s = 0.f; int cc = 0;
        for (int i = 0; i < k; i++) {
            float z = c[i];
            if (z > tau) { s += z; cc++; }
        }
        if (cc == prevc || cc == 0) break;
        tau = (s - 1.0f) / (float)cc;
        prevc = cc;
    }
    return tau;
}

__device__ float michelot_row_global(const float* xr, const int* mr) {
    // Fallback (statistically unreachable): serial Michelot over full row.
    float S = 0.f; int k = 0;
    for (int i = 0; i < DCOLS; i++) if (mr[i]) { S += xr[i]; k++; }
    float tau = (S - 1.0f) / (float)k;
    int prevc = k;
    for (int it = 0; it < DCOLS + 2; it++) {
        float s = 0.f; int cc = 0;
        for (int i = 0; i < DCOLS; i++) {
            if (mr[i]) { float z = xr[i]; if (z > tau) { s += z; cc++; } }
        }
        if (cc == prevc || cc == 0) break;
        tau = (s - 1.0f) / (float)cc;
        prevc = cc;
    }
    return tau;
}

__global__ __launch_bounds__(THREADS, 8) void sparsemax_kernel(
    const float* __restrict__ x,
    const int* __restrict__ mask,
    float* __restrict__ out)
{
    const int row = blockIdx.x;
    const int t = threadIdx.x;
    const int warp = t >> 5, lane = t & 31;

    const float4* xr = reinterpret_cast<const float4*>(x + (size_t)row * DCOLS);
    const int4*   mr = reinterpret_cast<const int4*>(mask + (size_t)row * DCOLS);
    float4* orow = reinterpret_cast<float4*>(out + (size_t)row * DCOLS);

    __shared__ float s_wmax[8];
    __shared__ int   s_cnt;
    __shared__ float s_tau;
    __shared__ float s_cand[CAP];

    // Load 8 values + 8 mask words, fold mask immediately: inactive -> -inf.
    float4 v0 = xr[t];
    float4 v1 = xr[t + THREADS];
    int4 m0 = mr[t];
    int4 m1 = mr[t + THREADS];

    float vals[8];
    vals[0] = m0.x ? v0.x : -CUDART_INF_F;
    vals[1] = m0.y ? v0.y : -CUDART_INF_F;
    vals[2] = m0.z ? v0.z : -CUDART_INF_F;
    vals[3] = m0.w ? v0.w : -CUDART_INF_F;
    vals[4] = m1.x ? v1.x : -CUDART_INF_F;
    vals[5] = m1.y ? v1.y : -CUDART_INF_F;
    vals[6] = m1.z ? v1.z : -CUDART_INF_F;
    vals[7] = m1.w ? v1.w : -CUDART_INF_F;

    // ---- Phase 1: block max (max alone decides: max is always a candidate) ----
    float mx = vals[0];
    #pragma unroll
    for (int i = 1; i < 8; i++) mx = fmaxf(mx, vals[i]);
    #pragma unroll
    for (int o = 16; o; o >>= 1)
        mx = fmaxf(mx, __shfl_xor_sync(0xFFFFFFFFu, mx, o));
    if (lane == 0) s_wmax[warp] = mx;
    if (t == 0) s_cnt = 0;
    __syncthreads();
    float allmax = s_wmax[0];
    #pragma unroll
    for (int i = 1; i < 8; i++) allmax = fmaxf(allmax, s_wmax[i]);

    // ---- Phase 2: warp-aggregated compaction of {v > max-1} ----
    // (if row is all-inactive: allmax=-inf, thresh=-inf, -inf > -inf false -> k=0)
    const float thresh = allmax - 1.0f;
    #pragma unroll
    for (int i = 0; i < 8; i++) {
        const bool p = vals[i] > thresh;
        const unsigned b = __ballot_sync(0xFFFFFFFFu, p);
        if (b) {
            const int leader = __ffs(b) - 1;
            int base = 0;
            if (lane == leader) base = atomicAdd(&s_cnt, __popc(b));
            base = __shfl_sync(0xFFFFFFFFu, base, leader);
            if (p) {
                int idx = base + __popc(b & ((1u << lane) - 1u));
                if (idx < CAP) s_cand[idx] = vals[i];
            }
        }
    }
    __syncthreads();
    const int k = s_cnt;

    // ---- Phase 3: exact threshold (serial, tiny candidate set) ----
    if (t == 0) {
        float tau;
        if (k == 0)        tau = CUDART_INF_F;            // all-inactive row -> zeros
        else if (k <= CAP) tau = michelot_list(s_cand, k);
        else               tau = michelot_row_global(x + (size_t)row * DCOLS,
                                                     mask + (size_t)row * DCOLS);
        s_tau = tau;
    }
    __syncthreads();
    const float tau = s_tau;

    // ---- Phase 4: p = relu(v - tau); -inf entries give 0 automatically ----
    float4 o0, o1;
    o0.x = fmaxf(vals[0] - tau, 0.f);
    o0.y = fmaxf(vals[1] - tau, 0.f);
    o0.z = fmaxf(vals[2] - tau, 0.f);
    o0.w = fmaxf(vals[3] - tau, 0.f);
    o1.x = fmaxf(vals[4] - tau, 0.f);
    o1.y = fmaxf(vals[5] - tau, 0.f);
    o1.z = fmaxf(vals[6] - tau, 0.f);
    o1.w = fmaxf(vals[7] - tau, 0.f);
    orow[t] = o0;
    orow[t + THREADS] = o1;
}

extern "C" void kernel_launch(void* const* d_in, const int* in_sizes, int n_in,
                              void* d_out, int out_size) {
    const float* x = (const float*)d_in[0];
    const int* mask = (const int*)d_in[1];
    float* out = (float*)d_out;

    const int rows = out_size / DCOLS;   // 16384
    sparsemax_kernel<<<rows, THREADS>>>(x, mask, out);
}